// round 2
// baseline (speedup 1.0000x reference)
#include <cuda_runtime.h>
#include <math.h>

#define BATCH 4
#define SEQL  2048
#define DIM   768
#define NST   16
#define BL    (BATCH*SEQL)

#define TL 64
#define KC 32

// scratch (static device globals — no runtime allocation)
__device__ float g_delta[BL];
// l-tiled n-major layout: element (pos p, state n) lives at (p>>2)*64 + n*4 + (p&3)
__device__ float g_Bt[NST*BL];
__device__ float g_Ct[NST*BL];

__device__ __forceinline__ float ex2f(float x) {
    float y;
    asm("ex2.approx.ftz.f32 %0, %1;" : "=f"(y) : "f"(x));
    return y;
}

// ---------------- kernel 1a: delta[b*l] = softplus(p_delta + u . q_delta) ----
__global__ void delta_kernel(const float* __restrict__ u,
                             const float* __restrict__ q_delta,
                             const float* __restrict__ p_delta) {
    int warp = (blockIdx.x * blockDim.x + threadIdx.x) >> 5;
    int lane = threadIdx.x & 31;
    if (warp >= BL) return;
    const float* up = u + (size_t)warp * DIM;
    float s = 0.f;
#pragma unroll
    for (int j = 0; j < 6; j++) {
        float4 uv = *(const float4*)(up      + j*128 + lane*4);
        float4 qv = *(const float4*)(q_delta + j*128 + lane*4);
        s = fmaf(uv.x, qv.x, s);
        s = fmaf(uv.y, qv.y, s);
        s = fmaf(uv.z, qv.z, s);
        s = fmaf(uv.w, qv.w, s);
    }
#pragma unroll
    for (int o = 16; o; o >>= 1) s += __shfl_xor_sync(0xffffffffu, s, o);
    if (lane == 0) {
        float z = s + p_delta[0];
        g_delta[warp] = (z > 20.f) ? z : log1pf(__expf(z));
    }
}

// ---------------- kernel 1b: Bt/Ct tiles = W_B/W_C @ u^T ---------------------
// logical out[32][8192]; stored in l-tiled n-major layout for the scan.
__global__ void proj_kernel(const float* __restrict__ u,
                            const float* __restrict__ W_B,
                            const float* __restrict__ W_C) {
    __shared__ __align__(16) float Us[KC*68];  // [k][pos], pad 68
    __shared__ __align__(16) float Ws[KC*36];  // [k][j],  pad 36
    int t  = threadIdx.x;       // 128 threads
    int tx = t & 15;            // pos group (4 pos)
    int ty = t >> 4;            // j group  (4 j), 0..7
    int blb = blockIdx.x * TL;  // position base

    float acc[4][4];
#pragma unroll
    for (int a = 0; a < 4; a++)
#pragma unroll
        for (int c = 0; c < 4; c++) acc[a][c] = 0.f;

    for (int dc = 0; dc < DIM; dc += KC) {
#pragma unroll
        for (int it = 0; it < (TL*KC)/128; it++) {
            int idx = t + it*128;
            int k = idx & 31, p = idx >> 5;
            Us[k*68 + p] = u[(size_t)(blb + p)*DIM + dc + k];
        }
#pragma unroll
        for (int it = 0; it < (32*KC)/128; it++) {
            int idx = t + it*128;
            int k = idx & 31, j = idx >> 5;
            const float* wr = (j < 16) ? (W_B + j*DIM) : (W_C + (j-16)*DIM);
            Ws[k*36 + j] = wr[dc + k];
        }
        __syncthreads();
#pragma unroll
        for (int k = 0; k < KC; k++) {
            float4 u4 = *(const float4*)(Us + k*68 + tx*4);
            float4 w4 = *(const float4*)(Ws + k*36 + ty*4);
            float us[4] = {u4.x, u4.y, u4.z, u4.w};
            float ws[4] = {w4.x, w4.y, w4.z, w4.w};
#pragma unroll
            for (int a = 0; a < 4; a++)
#pragma unroll
                for (int c = 0; c < 4; c++)
                    acc[a][c] = fmaf(ws[a], us[c], acc[a][c]);
        }
        __syncthreads();
    }
    // acc[a][0..3] = 4 consecutive positions for state j -> exactly one tile float4
#pragma unroll
    for (int a = 0; a < 4; a++) {
        int j = ty*4 + a;
        float* dst = (j < 16) ? g_Bt : g_Ct;
        int jj = (j < 16) ? j : j - 16;
        float4 v = make_float4(acc[a][0], acc[a][1], acc[a][2], acc[a][3]);
        *(float4*)(dst + (size_t)(blb + tx*4)*16 + jj*4) = v;
    }
}

// ---------------- kernel 2: selective scan -----------------------------------
// lane = n (16 lanes per (b,d) group, 2 groups per warp); x in register;
// B/C read as one float4 per lane per 4 timesteps (contiguous 256B per group).
__global__ void __launch_bounds__(128) scan_kernel(const float* __restrict__ u,
                            const float* __restrict__ A,
                            float* __restrict__ y) {
    int tid = blockIdx.x * blockDim.x + threadIdx.x;
    int g = tid >> 4;       // (b,d) group
    int n = tid & 15;
    int b = g / DIM;
    int d = g - b * DIM;

    float a2 = A[d*NST + n] * 1.4426950408889634f;  // fold log2(e)
    int base = b * SEQL;
    const float* dp = g_delta + base;
    const float* Bp = g_Bt + (size_t)base*16 + n*4;
    const float* Cp = g_Ct + (size_t)base*16 + n*4;
    const float* up = u + (size_t)base*DIM + d;
    float*       yp = y + (size_t)base*DIM + d;

    float x = 0.f;
    for (int l = 0; l < SEQL; l += 4) {
        float4 d4 = *(const float4*)(dp + l);
        float4 b4 = *(const float4*)(Bp + (size_t)l*16);
        float4 c4 = *(const float4*)(Cp + (size_t)l*16);
        float dls[4] = {d4.x, d4.y, d4.z, d4.w};
        float bs[4]  = {b4.x, b4.y, b4.z, b4.w};
        float cs[4]  = {c4.x, c4.y, c4.z, c4.w};
#pragma unroll
        for (int j = 0; j < 4; j++) {
            float ul = up[(size_t)(l+j)*DIM];
            float dA = ex2f(dls[j] * a2);
            x = fmaf(dA, x, dls[j] * ul * bs[j]);
            float p = x * cs[j];
            p += __shfl_xor_sync(0xffffffffu, p, 1);
            p += __shfl_xor_sync(0xffffffffu, p, 2);
            p += __shfl_xor_sync(0xffffffffu, p, 4);
            p += __shfl_xor_sync(0xffffffffu, p, 8);
            if (n == 0) yp[(size_t)(l+j)*DIM] = p;
        }
    }
}

extern "C" void kernel_launch(void* const* d_in, const int* in_sizes, int n_in,
                              void* d_out, int out_size) {
    const float* u       = (const float*)d_in[0];
    const float* A       = (const float*)d_in[1];
    const float* W_B     = (const float*)d_in[2];
    const float* W_C     = (const float*)d_in[3];
    const float* q_delta = (const float*)d_in[4];
    const float* p_delta = (const float*)d_in[5];
    float* y = (float*)d_out;

    delta_kernel<<<BL/8, 256>>>(u, q_delta, p_delta);
    proj_kernel<<<BL/TL, 128>>>(u, W_B, W_C);
    scan_kernel<<<(BATCH*DIM*NST)/128, 128>>>(u, A, y);
}

// round 3
// speedup vs baseline: 3.2468x; 3.2468x over previous
#include <cuda_runtime.h>
#include <math.h>

#define BATCH 4
#define SEQL  2048
#define DIM   768
#define NST   16
#define BL    (BATCH*SEQL)
#define NCH   16
#define CL    (SEQL/NCH)   // 128

#define TL 64
#define KC 32
#define LOG2E 1.4426950408889634f

// scratch (static device globals — no runtime allocation)
__device__ float g_delta[BL];
__device__ float g_sdelta[BATCH*NCH];
__device__ float g_Bt[BL*NST];   // [pos][n]
__device__ float g_Ct[BL*NST];   // [pos][n]
__device__ float g_xend [BATCH*DIM*NCH*NST];  // [(b*DIM+d)*NCH + c][n]
__device__ float g_xinit[BATCH*DIM*NCH*NST];

__device__ __forceinline__ float ex2f(float x) {
    float y;
    asm("ex2.approx.ftz.f32 %0, %1;" : "=f"(y) : "f"(x));
    return y;
}

// ---------------- kernel 1a: delta[b*l] = softplus(p_delta + u . q_delta) ----
__global__ void delta_kernel(const float* __restrict__ u,
                             const float* __restrict__ q_delta,
                             const float* __restrict__ p_delta) {
    int warp = (blockIdx.x * blockDim.x + threadIdx.x) >> 5;
    int lane = threadIdx.x & 31;
    if (warp >= BL) return;
    const float* up = u + (size_t)warp * DIM;
    float s = 0.f;
#pragma unroll
    for (int j = 0; j < 6; j++) {
        float4 uv = *(const float4*)(up      + j*128 + lane*4);
        float4 qv = *(const float4*)(q_delta + j*128 + lane*4);
        s = fmaf(uv.x, qv.x, s);
        s = fmaf(uv.y, qv.y, s);
        s = fmaf(uv.z, qv.z, s);
        s = fmaf(uv.w, qv.w, s);
    }
#pragma unroll
    for (int o = 16; o; o >>= 1) s += __shfl_xor_sync(0xffffffffu, s, o);
    if (lane == 0) {
        float z = s + p_delta[0];
        g_delta[warp] = (z > 20.f) ? z : log1pf(__expf(z));
    }
}

// ---------------- kernel 1b: per-(b,chunk) delta sums ------------------------
__global__ void sdelta_kernel() {
    __shared__ float ws[4];
    int bc = blockIdx.x;            // b*NCH + c
    int t = threadIdx.x;            // 128 threads
    float v = g_delta[bc*CL + t];
#pragma unroll
    for (int o = 16; o; o >>= 1) v += __shfl_xor_sync(0xffffffffu, v, o);
    if ((t & 31) == 0) ws[t >> 5] = v;
    __syncthreads();
    if (t == 0) g_sdelta[bc] = ws[0] + ws[1] + ws[2] + ws[3];
}

// ---------------- kernel 2: Bt/Ct = W_B/W_C @ u^T, stored [pos][n] -----------
__global__ void proj_kernel(const float* __restrict__ u,
                            const float* __restrict__ W_B,
                            const float* __restrict__ W_C) {
    __shared__ __align__(16) float Us[KC*68];
    __shared__ __align__(16) float Ws[KC*36];
    __shared__ __align__(16) float Bo[TL*NST];
    __shared__ __align__(16) float Co[TL*NST];
    int t  = threadIdx.x;       // 128 threads
    int tx = t & 15;
    int ty = t >> 4;
    int blb = blockIdx.x * TL;

    float acc[4][4];
#pragma unroll
    for (int a = 0; a < 4; a++)
#pragma unroll
        for (int c = 0; c < 4; c++) acc[a][c] = 0.f;

    for (int dc = 0; dc < DIM; dc += KC) {
#pragma unroll
        for (int it = 0; it < (TL*KC)/128; it++) {
            int idx = t + it*128;
            int k = idx & 31, p = idx >> 5;
            Us[k*68 + p] = u[(size_t)(blb + p)*DIM + dc + k];
        }
#pragma unroll
        for (int it = 0; it < (32*KC)/128; it++) {
            int idx = t + it*128;
            int k = idx & 31, j = idx >> 5;
            const float* wr = (j < 16) ? (W_B + j*DIM) : (W_C + (j-16)*DIM);
            Ws[k*36 + j] = wr[dc + k];
        }
        __syncthreads();
#pragma unroll
        for (int k = 0; k < KC; k++) {
            float4 u4 = *(const float4*)(Us + k*68 + tx*4);
            float4 w4 = *(const float4*)(Ws + k*36 + ty*4);
            float us[4] = {u4.x, u4.y, u4.z, u4.w};
            float ws4[4] = {w4.x, w4.y, w4.z, w4.w};
#pragma unroll
            for (int a = 0; a < 4; a++)
#pragma unroll
                for (int c = 0; c < 4; c++)
                    acc[a][c] = fmaf(ws4[a], us[c], acc[a][c]);
        }
        __syncthreads();
    }
    // transpose through smem to [pos][n]
#pragma unroll
    for (int a = 0; a < 4; a++) {
        int j = ty*4 + a;
        float* o = (j < 16) ? Bo : Co;
        int jj = j & 15;
#pragma unroll
        for (int c = 0; c < 4; c++)
            o[(tx*4 + c)*NST + jj] = acc[a][c];
    }
    __syncthreads();
#pragma unroll
    for (int it = 0; it < (TL*NST)/(128*4); it++) {
        int i = (t + it*128)*4;
        *(float4*)(g_Bt + (size_t)blb*NST + i) = *(const float4*)(Bo + i);
        *(float4*)(g_Ct + (size_t)blb*NST + i) = *(const float4*)(Co + i);
    }
}

// ---------------- kernel 3: local chunk scans (x0 = 0) -> x_end --------------
__global__ void __launch_bounds__(256) scan_init_kernel(const float* __restrict__ u,
                                                        const float* __restrict__ A) {
    __shared__ float ds[CL];
    __shared__ __align__(16) float Bs[CL*NST];
    int t = threadIdx.x;
    int b = blockIdx.z, c = blockIdx.y;
    int d = blockIdx.x * 256 + t;
    int pos0 = b*SEQL + c*CL;

    if (t < CL) ds[t] = g_delta[pos0 + t];
#pragma unroll
    for (int i = t; i < CL*NST/4; i += 256)
        *(float4*)(Bs + i*4) = *(const float4*)(g_Bt + (size_t)pos0*NST + i*4);
    __syncthreads();

    float A2[NST];
#pragma unroll
    for (int k = 0; k < 4; k++) {
        float4 a4 = *(const float4*)(A + d*NST + k*4);
        A2[k*4+0] = a4.x*LOG2E; A2[k*4+1] = a4.y*LOG2E;
        A2[k*4+2] = a4.z*LOG2E; A2[k*4+3] = a4.w*LOG2E;
    }
    float x[NST];
#pragma unroll
    for (int k = 0; k < NST; k++) x[k] = 0.f;

    const float* up = u + (size_t)pos0*DIM + d;
#pragma unroll 4
    for (int l = 0; l < CL; l++) {
        float dl = ds[l];
        float du = dl * up[(size_t)l*DIM];
        const float4* bp = (const float4*)(Bs + l*NST);
#pragma unroll
        for (int k = 0; k < 4; k++) {
            float4 b4 = bp[k];
            x[k*4+0] = fmaf(ex2f(dl*A2[k*4+0]), x[k*4+0], du*b4.x);
            x[k*4+1] = fmaf(ex2f(dl*A2[k*4+1]), x[k*4+1], du*b4.y);
            x[k*4+2] = fmaf(ex2f(dl*A2[k*4+2]), x[k*4+2], du*b4.z);
            x[k*4+3] = fmaf(ex2f(dl*A2[k*4+3]), x[k*4+3], du*b4.w);
        }
    }
    float* xe = g_xend + (((size_t)b*DIM + d)*NCH + c)*NST;
#pragma unroll
    for (int k = 0; k < 4; k++)
        *(float4*)(xe + k*4) = make_float4(x[k*4], x[k*4+1], x[k*4+2], x[k*4+3]);
}

// ---------------- kernel 4: serial chain over chunks -> x_init ---------------
__global__ void chain_kernel(const float* __restrict__ A) {
    int t = blockIdx.x * blockDim.x + threadIdx.x;   // (b*DIM+d)*NST + n
    int n = t & 15;
    int bd = t >> 4;
    int b = bd / DIM;
    int d = bd - b*DIM;
    float A2 = A[d*NST + n] * LOG2E;
    float x = 0.f;
#pragma unroll
    for (int c = 0; c < NCH; c++) {
        size_t idx = ((size_t)bd*NCH + c)*NST + n;
        g_xinit[idx] = x;
        float P = ex2f(A2 * g_sdelta[b*NCH + c]);
        x = fmaf(P, x, g_xend[idx]);
    }
}

// ---------------- kernel 5: main scan with correct init, emit y --------------
__global__ void __launch_bounds__(256) scan_main_kernel(const float* __restrict__ u,
                                                        const float* __restrict__ A,
                                                        float* __restrict__ y) {
    __shared__ float ds[CL];
    __shared__ __align__(16) float Bs[CL*NST];
    __shared__ __align__(16) float Cs[CL*NST];
    int t = threadIdx.x;
    int b = blockIdx.z, c = blockIdx.y;
    int d = blockIdx.x * 256 + t;
    int pos0 = b*SEQL + c*CL;

    if (t < CL) ds[t] = g_delta[pos0 + t];
#pragma unroll
    for (int i = t; i < CL*NST/4; i += 256) {
        *(float4*)(Bs + i*4) = *(const float4*)(g_Bt + (size_t)pos0*NST + i*4);
        *(float4*)(Cs + i*4) = *(const float4*)(g_Ct + (size_t)pos0*NST + i*4);
    }
    __syncthreads();

    float A2[NST];
#pragma unroll
    for (int k = 0; k < 4; k++) {
        float4 a4 = *(const float4*)(A + d*NST + k*4);
        A2[k*4+0] = a4.x*LOG2E; A2[k*4+1] = a4.y*LOG2E;
        A2[k*4+2] = a4.z*LOG2E; A2[k*4+3] = a4.w*LOG2E;
    }
    float x[NST];
    const float* xi = g_xinit + (((size_t)b*DIM + d)*NCH + c)*NST;
#pragma unroll
    for (int k = 0; k < 4; k++) {
        float4 v = *(const float4*)(xi + k*4);
        x[k*4] = v.x; x[k*4+1] = v.y; x[k*4+2] = v.z; x[k*4+3] = v.w;
    }

    const float* up = u + (size_t)pos0*DIM + d;
    float*       yp = y + (size_t)pos0*DIM + d;
#pragma unroll 4
    for (int l = 0; l < CL; l++) {
        float dl = ds[l];
        float du = dl * up[(size_t)l*DIM];
        const float4* bp = (const float4*)(Bs + l*NST);
        const float4* cp = (const float4*)(Cs + l*NST);
        float acc = 0.f;
#pragma unroll
        for (int k = 0; k < 4; k++) {
            float4 b4 = bp[k];
            float4 c4 = cp[k];
            x[k*4+0] = fmaf(ex2f(dl*A2[k*4+0]), x[k*4+0], du*b4.x);
            x[k*4+1] = fmaf(ex2f(dl*A2[k*4+1]), x[k*4+1], du*b4.y);
            x[k*4+2] = fmaf(ex2f(dl*A2[k*4+2]), x[k*4+2], du*b4.z);
            x[k*4+3] = fmaf(ex2f(dl*A2[k*4+3]), x[k*4+3], du*b4.w);
            acc = fmaf(x[k*4+0], c4.x, acc);
            acc = fmaf(x[k*4+1], c4.y, acc);
            acc = fmaf(x[k*4+2], c4.z, acc);
            acc = fmaf(x[k*4+3], c4.w, acc);
        }
        yp[(size_t)l*DIM] = acc;
    }
}

extern "C" void kernel_launch(void* const* d_in, const int* in_sizes, int n_in,
                              void* d_out, int out_size) {
    const float* u       = (const float*)d_in[0];
    const float* A       = (const float*)d_in[1];
    const float* W_B     = (const float*)d_in[2];
    const float* W_C     = (const float*)d_in[3];
    const float* q_delta = (const float*)d_in[4];
    const float* p_delta = (const float*)d_in[5];
    float* y = (float*)d_out;

    delta_kernel<<<BL/8, 256>>>(u, q_delta, p_delta);
    proj_kernel<<<BL/TL, 128>>>(u, W_B, W_C);
    sdelta_kernel<<<BATCH*NCH, CL>>>();
    scan_init_kernel<<<dim3(DIM/256, NCH, BATCH), 256>>>(u, A);
    chain_kernel<<<(BATCH*DIM*NST)/256, 256>>>(A);
    scan_main_kernel<<<dim3(DIM/256, NCH, BATCH), 256>>>(u, A, y);
}

// round 5
// speedup vs baseline: 3.2963x; 1.0152x over previous
#include <cuda_runtime.h>
#include <math.h>

#define BATCH 4
#define SEQL  2048
#define DIM   768
#define NST   16
#define BL    (BATCH*SEQL)
#define NCH   32
#define CL    (SEQL/NCH)   // 64

#define TL 64              // == CL: one proj block == one chunk
#define KC 32
#define LOG2E 1.4426950408889634f

// scratch (static device globals — no runtime allocation)
__device__ float g_delta[BL];
__device__ float g_sdelta[BATCH*NCH];
__device__ float g_Bt[BL*NST];   // [pos][n]
__device__ float g_Ct[BL*NST];   // [pos][n]
__device__ float g_xend [BATCH*DIM*NCH*NST];  // [(b*DIM+d)*NCH + c][n]
__device__ float g_xinit[BATCH*DIM*NCH*NST];

__device__ __forceinline__ float ex2f(float x) {
    float y;
    asm("ex2.approx.ftz.f32 %0, %1;" : "=f"(y) : "f"(x));
    return y;
}

// ---- kernel 1: proj + fused delta/softplus + chunk delta-sums ---------------
// Bt/Ct = W_B/W_C @ u^T stored [pos][n]; delta = softplus(p + u.q); sdelta per chunk.
__global__ void proj_kernel(const float* __restrict__ u,
                            const float* __restrict__ W_B,
                            const float* __restrict__ W_C,
                            const float* __restrict__ q_delta,
                            const float* __restrict__ p_delta) {
    __shared__ __align__(16) float Us[KC*68];
    __shared__ __align__(16) float Ws[KC*36];   // cols 0..31 = W rows, col 32 = q_delta
    __shared__ __align__(16) float Bo[TL*NST];
    __shared__ __align__(16) float Co[TL*NST];
    int t  = threadIdx.x;       // 128 threads
    int tx = t & 15;
    int ty = t >> 4;
    int blb = blockIdx.x * TL;

    float acc[4][4];
    float dacc[4] = {0.f, 0.f, 0.f, 0.f};
#pragma unroll
    for (int a = 0; a < 4; a++)
#pragma unroll
        for (int c = 0; c < 4; c++) acc[a][c] = 0.f;

    for (int dc = 0; dc < DIM; dc += KC) {
#pragma unroll
        for (int it = 0; it < (TL*KC)/128; it++) {
            int idx = t + it*128;
            int k = idx & 31, p = idx >> 5;
            Us[k*68 + p] = u[(size_t)(blb + p)*DIM + dc + k];
        }
#pragma unroll
        for (int it = 0; it < (32*KC)/128; it++) {
            int idx = t + it*128;
            int k = idx & 31, j = idx >> 5;
            const float* wr = (j < 16) ? (W_B + j*DIM) : (W_C + (j-16)*DIM);
            Ws[k*36 + j] = wr[dc + k];
        }
        if (t < 32) Ws[t*36 + 32] = q_delta[dc + t];
        __syncthreads();
#pragma unroll
        for (int k = 0; k < KC; k++) {
            float4 u4 = *(const float4*)(Us + k*68 + tx*4);
            float4 w4 = *(const float4*)(Ws + k*36 + ty*4);
            float us[4] = {u4.x, u4.y, u4.z, u4.w};
            float ws4[4] = {w4.x, w4.y, w4.z, w4.w};
#pragma unroll
            for (int a = 0; a < 4; a++)
#pragma unroll
                for (int c = 0; c < 4; c++)
                    acc[a][c] = fmaf(ws4[a], us[c], acc[a][c]);
            if (ty == 0) {
                float qk = Ws[k*36 + 32];
#pragma unroll
                for (int c = 0; c < 4; c++)
                    dacc[c] = fmaf(qk, us[c], dacc[c]);
            }
        }
        __syncthreads();
    }
    // delta epilogue — lanes 0..15 of warp 0 only; mask names exactly those lanes
    if (ty == 0) {
        float p0 = p_delta[0];
        float s = 0.f;
#pragma unroll
        for (int c = 0; c < 4; c++) {
            float z = dacc[c] + p0;
            float sp = (z > 20.f) ? z : log1pf(__expf(z));
            g_delta[blb + tx*4 + c] = sp;
            s += sp;
        }
#pragma unroll
        for (int o = 8; o; o >>= 1) s += __shfl_xor_sync(0xffffu, s, o);
        if (tx == 0) g_sdelta[blockIdx.x] = s;   // blockIdx.x == b*NCH + c
    }
    // transpose B/C through smem to [pos][n]
#pragma unroll
    for (int a = 0; a < 4; a++) {
        int j = ty*4 + a;
        float* o = (j < 16) ? Bo : Co;
        int jj = j & 15;
#pragma unroll
        for (int c = 0; c < 4; c++)
            o[(tx*4 + c)*NST + jj] = acc[a][c];
    }
    __syncthreads();
#pragma unroll
    for (int it = 0; it < (TL*NST)/(128*4); it++) {
        int i = (t + it*128)*4;
        *(float4*)(g_Bt + (size_t)blb*NST + i) = *(const float4*)(Bo + i);
        *(float4*)(g_Ct + (size_t)blb*NST + i) = *(const float4*)(Co + i);
    }
}

// ---- kernel 2: local chunk scans (x0 = 0) -> x_end --------------------------
__global__ void __launch_bounds__(128) scan_init_kernel(const float* __restrict__ u,
                                                        const float* __restrict__ A) {
    __shared__ float ds[CL];
    __shared__ __align__(16) float Bs[CL*NST];
    int t = threadIdx.x;
    int b = blockIdx.z, c = blockIdx.y;
    int d = blockIdx.x * 128 + t;
    int pos0 = b*SEQL + c*CL;

    if (t < CL) ds[t] = g_delta[pos0 + t];
#pragma unroll
    for (int i = t; i < CL*NST/4; i += 128)
        *(float4*)(Bs + i*4) = *(const float4*)(g_Bt + (size_t)pos0*NST + i*4);
    __syncthreads();

    float A2[NST];
#pragma unroll
    for (int k = 0; k < 4; k++) {
        float4 a4 = *(const float4*)(A + d*NST + k*4);
        A2[k*4+0] = a4.x*LOG2E; A2[k*4+1] = a4.y*LOG2E;
        A2[k*4+2] = a4.z*LOG2E; A2[k*4+3] = a4.w*LOG2E;
    }
    float x[NST];
#pragma unroll
    for (int k = 0; k < NST; k++) x[k] = 0.f;

    const float* up = u + (size_t)pos0*DIM + d;
#pragma unroll 4
    for (int l = 0; l < CL; l++) {
        float dl = ds[l];
        float du = dl * up[(size_t)l*DIM];
        const float4* bp = (const float4*)(Bs + l*NST);
#pragma unroll
        for (int k = 0; k < 4; k++) {
            float4 b4 = bp[k];
            x[k*4+0] = fmaf(ex2f(dl*A2[k*4+0]), x[k*4+0], du*b4.x);
            x[k*4+1] = fmaf(ex2f(dl*A2[k*4+1]), x[k*4+1], du*b4.y);
            x[k*4+2] = fmaf(ex2f(dl*A2[k*4+2]), x[k*4+2], du*b4.z);
            x[k*4+3] = fmaf(ex2f(dl*A2[k*4+3]), x[k*4+3], du*b4.w);
        }
    }
    float* xe = g_xend + (((size_t)b*DIM + d)*NCH + c)*NST;
#pragma unroll
    for (int k = 0; k < 4; k++)
        *(float4*)(xe + k*4) = make_float4(x[k*4], x[k*4+1], x[k*4+2], x[k*4+3]);
}

// ---- kernel 3: serial chain over chunks -> x_init ---------------------------
__global__ void chain_kernel(const float* __restrict__ A) {
    int t = blockIdx.x * blockDim.x + threadIdx.x;   // (b*DIM+d)*NST + n
    int n = t & 15;
    int bd = t >> 4;
    int b = bd / DIM;
    int d = bd - b*DIM;
    float A2 = A[d*NST + n] * LOG2E;
    float x = 0.f;
#pragma unroll
    for (int c = 0; c < NCH; c++) {
        size_t idx = ((size_t)bd*NCH + c)*NST + n;
        g_xinit[idx] = x;
        float P = ex2f(A2 * g_sdelta[b*NCH + c]);
        x = fmaf(P, x, g_xend[idx]);
    }
}

// ---- kernel 4: main scan with correct init, emit y --------------------------
__global__ void __launch_bounds__(128) scan_main_kernel(const float* __restrict__ u,
                                                        const float* __restrict__ A,
                                                        float* __restrict__ y) {
    __shared__ float ds[CL];
    __shared__ __align__(16) float Bs[CL*NST];
    __shared__ __align__(16) float Cs[CL*NST];
    int t = threadIdx.x;
    int b = blockIdx.z, c = blockIdx.y;
    int d = blockIdx.x * 128 + t;
    int pos0 = b*SEQL + c*CL;

    if (t < CL) ds[t] = g_delta[pos0 + t];
#pragma unroll
    for (int i = t; i < CL*NST/4; i += 128) {
        *(float4*)(Bs + i*4) = *(const float4*)(g_Bt + (size_t)pos0*NST + i*4);
        *(float4*)(Cs + i*4) = *(const float4*)(g_Ct + (size_t)pos0*NST + i*4);
    }
    __syncthreads();

    float A2[NST];
#pragma unroll
    for (int k = 0; k < 4; k++) {
        float4 a4 = *(const float4*)(A + d*NST + k*4);
        A2[k*4+0] = a4.x*LOG2E; A2[k*4+1] = a4.y*LOG2E;
        A2[k*4+2] = a4.z*LOG2E; A2[k*4+3] = a4.w*LOG2E;
    }
    float x[NST];
    const float* xi = g_xinit + (((size_t)b*DIM + d)*NCH + c)*NST;
#pragma unroll
    for (int k = 0; k < 4; k++) {
        float4 v = *(const float4*)(xi + k*4);
        x[k*4] = v.x; x[k*4+1] = v.y; x[k*4+2] = v.z; x[k*4+3] = v.w;
    }

    const float* up = u + (size_t)pos0*DIM + d;
    float*       yp = y + (size_t)pos0*DIM + d;
#pragma unroll 4
    for (int l = 0; l < CL; l++) {
        float dl = ds[l];
        float du = dl * up[(size_t)l*DIM];
        const float4* bp = (const float4*)(Bs + l*NST);
        const float4* cp = (const float4*)(Cs + l*NST);
        float acc = 0.f;
#pragma unroll
        for (int k = 0; k < 4; k++) {
            float4 b4 = bp[k];
            float4 c4 = cp[k];
            x[k*4+0] = fmaf(ex2f(dl*A2[k*4+0]), x[k*4+0], du*b4.x);
            x[k*4+1] = fmaf(ex2f(dl*A2[k*4+1]), x[k*4+1], du*b4.y);
            x[k*4+2] = fmaf(ex2f(dl*A2[k*4+2]), x[k*4+2], du*b4.z);
            x[k*4+3] = fmaf(ex2f(dl*A2[k*4+3]), x[k*4+3], du*b4.w);
            acc = fmaf(x[k*4+0], c4.x, acc);
            acc = fmaf(x[k*4+1], c4.y, acc);
            acc = fmaf(x[k*4+2], c4.z, acc);
            acc = fmaf(x[k*4+3], c4.w, acc);
        }
        yp[(size_t)l*DIM] = acc;
    }
}

extern "C" void kernel_launch(void* const* d_in, const int* in_sizes, int n_in,
                              void* d_out, int out_size) {
    const float* u       = (const float*)d_in[0];
    const float* A       = (const float*)d_in[1];
    const float* W_B     = (const float*)d_in[2];
    const float* W_C     = (const float*)d_in[3];
    const float* q_delta = (const float*)d_in[4];
    const float* p_delta = (const float*)d_in[5];
    float* y = (float*)d_out;

    proj_kernel<<<BL/TL, 128>>>(u, W_B, W_C, q_delta, p_delta);
    scan_init_kernel<<<dim3(DIM/128, NCH, BATCH), 128>>>(u, A);
    chain_kernel<<<(BATCH*DIM*NST)/256, 256>>>(A);
    scan_main_kernel<<<dim3(DIM/128, NCH, BATCH), 128>>>(u, A, y);
}